// round 12
// baseline (speedup 1.0000x reference)
#include <cuda_runtime.h>
#include <cuda_fp16.h>
#include <cstdint>

#define NN 50000
#define EE 500000
#define ET (EE + NN)
#define DD 256
#define HH 8
#define NEGS 0.2f

#define KS 512                  // A stored split-K: [0,256)=hi, [256,512)=lo (fp16)
#define KB 256                  // B stored single fp16
#define BM 128
#define BN 128
#define NCHUNK 8                // 2 passes x 4 chunks of K=64
#define NTILES ((NN + BM - 1) / BM)   // 391
#define MPAD (NTILES * BM)            // 50048
#define NB 196                  // scan blocks (ceil(NN/256))

// ---------------- scratch ----------------
__device__ __half g_A[(size_t)MPAD * KS];   // split activations
__device__ __half g_B[(size_t)DD * KB];     // fp16 weight, B^T layout [n][k]
__device__ float g_W01[DD * DD];            // fused projW@W1 (fp32)
__device__ float g_b01[DD];                 // proj_b@W1
__device__ float g_h[NN * DD];
__device__ float g_el[NN * HH];
__device__ float g_er[NN * HH];
__device__ int g_cnt[NN + 256];
__device__ int g_bsum[256];
__device__ int g_bpre[256];
__device__ int g_off[NN + 1];
__device__ int g_cur[NN];
__device__ int g_csr[ET];

__device__ __forceinline__ float leaky(float v) { return v > 0.f ? v : NEGS * v; }
__device__ __forceinline__ uint32_t smem_u32(const void* p) {
    return (uint32_t)__cvta_generic_to_shared(p);
}

// ---------------- fused weight: W01 = projW @ W1, b01 = proj_b @ W1 ----------------
__global__ void wfuse(const float* __restrict__ PW, const float* __restrict__ W1,
                      const float* __restrict__ pb, float* __restrict__ W01,
                      float* __restrict__ b01) {
    int m = blockIdx.x;          // 0..DD rows; block DD computes b01
    int n = threadIdx.x;
    if (m < DD) {
        float s = 0.f;
        #pragma unroll 4
        for (int j = 0; j < DD; j++)
            s += PW[m * DD + j] * W1[j * DD + n];
        W01[m * DD + n] = s;
    } else {
        float s = 0.f;
        #pragma unroll 4
        for (int j = 0; j < DD; j++)
            s += pb[j] * W1[j * DD + n];
        b01[n] = s;
    }
}

// ---------------- split kernels (fp32 -> fp16 hi/lo) ----------------
__global__ void split_act(const float* __restrict__ x, __half* __restrict__ A) {
    int i = blockIdx.x * blockDim.x + threadIdx.x;     // float4 idx
    if (i >= NN * DD / 4) return;
    int m = i >> 6, c = (i & 63) * 4;
    float4 v = ((const float4*)x)[i];
    __half2 h0 = __floats2half2_rn(v.x, v.y);
    __half2 h1 = __floats2half2_rn(v.z, v.w);
    __half2 l0 = __floats2half2_rn(v.x - __half2float(h0.x), v.y - __half2float(h0.y));
    __half2 l1 = __floats2half2_rn(v.z - __half2float(h1.x), v.w - __half2float(h1.y));
    __half2* p = (__half2*)(A + (size_t)m * KS + c);
    p[0] = h0; p[1] = h1;
    __half2* q = (__half2*)(A + (size_t)m * KS + 256 + c);
    q[0] = l0; q[1] = l1;
}
__global__ void split_w(const float* __restrict__ W, __half* __restrict__ Bm) {
    int i = blockIdx.x * blockDim.x + threadIdx.x;
    if (i >= DD * DD) return;
    int k = i >> 8, n = i & 255;           // W[k][n]
    Bm[(size_t)n * KB + k] = __float2half(W[i]);
}

// ---------------- CSR build ----------------
__global__ void csr_init(int* __restrict__ cnt) {
    int i = blockIdx.x * blockDim.x + threadIdx.x;
    if (i < NN) cnt[i] = 1;                 // self loop
}
__global__ void csr_hist(const int* __restrict__ dst, int* __restrict__ cnt) {
    int i = blockIdx.x * blockDim.x + threadIdx.x;
    if (i < EE) atomicAdd(&cnt[dst[i]], 1);
}
__global__ void csr_scan1(const int* __restrict__ cnt, int* __restrict__ bsum) {
    __shared__ int sd[256];
    int t = threadIdx.x, i = blockIdx.x * 256 + t;
    sd[t] = (i < NN) ? cnt[i] : 0;
    __syncthreads();
    for (int o = 128; o; o >>= 1) {
        if (t < o) sd[t] += sd[t + o];
        __syncthreads();
    }
    if (t == 0) bsum[blockIdx.x] = sd[0];
}
__global__ void csr_scan2(const int* __restrict__ bsum, int* __restrict__ bpre) {
    __shared__ int sd[256];
    int t = threadIdx.x;
    int v = (t < NB) ? bsum[t] : 0;
    sd[t] = v;
    __syncthreads();
    for (int o = 1; o < 256; o <<= 1) {
        int x = (t >= o) ? sd[t - o] : 0;
        __syncthreads();
        sd[t] += x;
        __syncthreads();
    }
    bpre[t] = sd[t] - v;                    // exclusive
}
__global__ void csr_scan3(const int* __restrict__ cnt, const int* __restrict__ bpre,
                          int* __restrict__ off, int* __restrict__ cur) {
    __shared__ int sd[256];
    int t = threadIdx.x, i = blockIdx.x * 256 + t;
    int v = (i < NN) ? cnt[i] : 0;
    sd[t] = v;
    __syncthreads();
    for (int o = 1; o < 256; o <<= 1) {
        int x = (t >= o) ? sd[t - o] : 0;
        __syncthreads();
        sd[t] += x;
        __syncthreads();
    }
    int ex = bpre[blockIdx.x] + sd[t] - v;
    if (i <= NN) {
        off[i] = ex;
        if (i < NN) cur[i] = ex;
    }
}
__global__ void csr_scatter(const int* __restrict__ src, const int* __restrict__ dst,
                            int* __restrict__ cur, int* __restrict__ csr) {
    int i = blockIdx.x * blockDim.x + threadIdx.x;
    if (i >= ET) return;
    int s = (i < EE) ? src[i] : (i - EE);
    int d = (i < EE) ? dst[i] : (i - EE);
    int pos = atomicAdd(&cur[d], 1);
    csr[pos] = s;
}

// ---------------- HMMA GEMM (BM=128, BN=128, 8 warps, 3-stage pipeline) ----------------
#define STG 32768

__device__ __forceinline__ void fill_stage(const __half* A, const __half* B,
                                           uint32_t aB, uint32_t bB,
                                           int m0, int n0, int c, int tid) {
    int kA = ((c >= 4) ? 256 : 0) + (c & 3) * 64;
    int kB = (c & 3) * 64;
    const char* Ag = (const char*)(A + (size_t)m0 * KS + kA);
    const char* Bg = (const char*)(B + (size_t)n0 * KB + kB);
    #pragma unroll
    for (int i = 0; i < 4; i++) {
        int u = tid + i * 256;
        int r = u >> 3, s = u & 7;
        uint32_t off = (uint32_t)r * 128 + (uint32_t)((s ^ (r & 7)) << 4);
        unsigned long long sa = __cvta_generic_to_global(Ag + (size_t)r * 1024 + s * 16);
        unsigned long long sbg = __cvta_generic_to_global(Bg + (size_t)r * 512 + s * 16);
        asm volatile("cp.async.cg.shared.global [%0], [%1], 16;" :: "r"(aB + off), "l"(sa));
        asm volatile("cp.async.cg.shared.global [%0], [%1], 16;" :: "r"(bB + off), "l"(sbg));
    }
}

__device__ __forceinline__ void mma16816(float* d, const uint32_t* a, const uint32_t* b) {
    asm volatile("mma.sync.aligned.m16n8k16.row.col.f32.f16.f16.f32 "
                 "{%0,%1,%2,%3}, {%4,%5,%6,%7}, {%8,%9}, {%0,%1,%2,%3};"
                 : "+f"(d[0]), "+f"(d[1]), "+f"(d[2]), "+f"(d[3])
                 : "r"(a[0]), "r"(a[1]), "r"(a[2]), "r"(a[3]), "r"(b[0]), "r"(b[1]));
}

__global__ void __launch_bounds__(256, 2)
gemm_fp16x2(const __half* __restrict__ A, const __half* __restrict__ B,
            const float* __restrict__ bias, float* __restrict__ outf,
            const float* __restrict__ al, const float* __restrict__ ar,
            float* __restrict__ el, float* __restrict__ er) {
    extern __shared__ char smem[];
    uint32_t sb = smem_u32(smem);
    int tid = threadIdx.x, wid = tid >> 5, lane = tid & 31;
    int m0 = blockIdx.y * BM, n0 = blockIdx.x * BN;
    int warp_m = (wid & 3) * 32, warp_n = (wid >> 2) * 64;

    float acc[2][8][4];
    #pragma unroll
    for (int mt = 0; mt < 2; mt++)
        #pragma unroll
        for (int nt = 0; nt < 8; nt++)
            #pragma unroll
            for (int q = 0; q < 4; q++) acc[mt][nt][q] = 0.f;

    // prologue: fill stages 0 and 1
    fill_stage(A, B, sb, sb + 16384, m0, n0, 0, tid);
    asm volatile("cp.async.commit_group;" ::: "memory");
    fill_stage(A, B, sb + STG, sb + STG + 16384, m0, n0, 1, tid);
    asm volatile("cp.async.commit_group;" ::: "memory");

    int st = 0;                                   // stage index = c % 3
    for (int c = 0; c < NCHUNK; c++) {
        if (c < NCHUNK - 1) asm volatile("cp.async.wait_group 1;" ::: "memory");
        else                asm volatile("cp.async.wait_group 0;" ::: "memory");
        __syncthreads();
        if (c + 2 < NCHUNK) {
            int fs = st + 2; if (fs >= 3) fs -= 3;
            uint32_t fb = sb + (uint32_t)fs * STG;
            fill_stage(A, B, fb, fb + 16384, m0, n0, c + 2, tid);
            asm volatile("cp.async.commit_group;" ::: "memory");
        }
        uint32_t as = sb + (uint32_t)st * STG;
        uint32_t bs = as + 16384;
        #pragma unroll
        for (int kk = 0; kk < 4; kk++) {
            uint32_t a[2][4], b[8][2];
            {
                int rr = lane & 15, half = lane >> 4;
                int s = kk * 2 + half;
                #pragma unroll
                for (int mt = 0; mt < 2; mt++) {
                    int row = warp_m + mt * 16 + rr;
                    uint32_t ad = as + (uint32_t)row * 128 + (uint32_t)((s ^ (row & 7)) << 4);
                    asm volatile("ldmatrix.sync.aligned.m8n8.x4.shared.b16 {%0,%1,%2,%3}, [%4];"
                                 : "=r"(a[mt][0]), "=r"(a[mt][1]), "=r"(a[mt][2]), "=r"(a[mt][3])
                                 : "r"(ad));
                }
            }
            {
                int half = (lane >> 3) & 1;
                int s = kk * 2 + half;
                int nro = ((lane >> 4) << 3) + (lane & 7);
                #pragma unroll
                for (int j = 0; j < 4; j++) {
                    int row = warp_n + j * 16 + nro;
                    uint32_t bd = bs + (uint32_t)row * 128 + (uint32_t)((s ^ (row & 7)) << 4);
                    asm volatile("ldmatrix.sync.aligned.m8n8.x4.shared.b16 {%0,%1,%2,%3}, [%4];"
                                 : "=r"(b[2*j][0]), "=r"(b[2*j][1]), "=r"(b[2*j+1][0]), "=r"(b[2*j+1][1])
                                 : "r"(bd));
                }
            }
            #pragma unroll
            for (int mt = 0; mt < 2; mt++)
                #pragma unroll
                for (int nt = 0; nt < 8; nt++)
                    mma16816(acc[mt][nt], a[mt], b[nt]);
        }
        if (++st == 3) st = 0;
    }

    // ---------------- epilogue ----------------
    int rin = lane >> 2, colq = (lane & 3) * 2;
    if (bias) {
        #pragma unroll
        for (int nt = 0; nt < 8; nt++) {
            int cb = n0 + warp_n + nt * 8 + colq;
            float b0 = __ldg(bias + cb), b1 = __ldg(bias + cb + 1);
            #pragma unroll
            for (int mt = 0; mt < 2; mt++) {
                acc[mt][nt][0] += b0; acc[mt][nt][1] += b1;
                acc[mt][nt][2] += b0; acc[mt][nt][3] += b1;
            }
        }
    }
    #pragma unroll
    for (int mt = 0; mt < 2; mt++) {
        int r0 = m0 + warp_m + mt * 16 + rin;
        #pragma unroll
        for (int nt = 0; nt < 8; nt++) {
            int cb = n0 + warp_n + nt * 8 + colq;
            if (r0 < NN)
                *(float2*)(outf + (size_t)r0 * DD + cb) =
                    make_float2(acc[mt][nt][0], acc[mt][nt][1]);
            if (r0 + 8 < NN)
                *(float2*)(outf + (size_t)(r0 + 8) * DD + cb) =
                    make_float2(acc[mt][nt][2], acc[mt][nt][3]);
        }
        #pragma unroll
        for (int hh2 = 0; hh2 < 2; hh2++) {
            int ghead = (n0 + warp_n + hh2 * 32) >> 5;
            float sl0 = 0.f, sr0 = 0.f, sl1 = 0.f, sr1 = 0.f;
            #pragma unroll
            for (int t = 0; t < 4; t++) {
                int nt = hh2 * 4 + t;
                int cg = n0 + warp_n + nt * 8 + colq;
                float w0 = __ldg(al + cg), w1 = __ldg(al + cg + 1);
                float u0 = __ldg(ar + cg), u1 = __ldg(ar + cg + 1);
                sl0 += acc[mt][nt][0] * w0 + acc[mt][nt][1] * w1;
                sr0 += acc[mt][nt][0] * u0 + acc[mt][nt][1] * u1;
                sl1 += acc[mt][nt][2] * w0 + acc[mt][nt][3] * w1;
                sr1 += acc[mt][nt][2] * u0 + acc[mt][nt][3] * u1;
            }
            #pragma unroll
            for (int o = 1; o < 4; o <<= 1) {
                sl0 += __shfl_xor_sync(0xffffffffu, sl0, o);
                sr0 += __shfl_xor_sync(0xffffffffu, sr0, o);
                sl1 += __shfl_xor_sync(0xffffffffu, sl1, o);
                sr1 += __shfl_xor_sync(0xffffffffu, sr1, o);
            }
            if (colq == 0) {
                if (r0 < NN) { el[r0 * HH + ghead] = sl0; er[r0 * HH + ghead] = sr0; }
                if (r0 + 8 < NN) { el[(r0 + 8) * HH + ghead] = sl1; er[(r0 + 8) * HH + ghead] = sr1; }
            }
        }
    }
}

// ---------------- CSR aggregation: block per dst node, 64 threads ----------------
__global__ void __launch_bounds__(64)
agg_node(const int* __restrict__ off, const int* __restrict__ csr,
         const float* __restrict__ el, const float* __restrict__ er,
         const float* __restrict__ h, const float* __restrict__ bias,
         float* __restrict__ outf, __half* __restrict__ outA) {
    int d = blockIdx.x;
    int tid = threadIdx.x, w = tid >> 5, lane = tid & 31;
    int beg = __ldg(off + d), end = __ldg(off + d + 1);
    int hloc = lane >> 3;
    float erv = (lane < 4) ? __ldg(er + d * HH + w * 4 + lane) : 0.f;
    float4 acc = make_float4(0.f, 0.f, 0.f, 0.f);
    float zacc = 0.f;
    for (int j = beg; j < end; j++) {
        int s = __ldg(csr + j);
        float aexp = 0.f;
        if (lane < 4) {
            float e = __ldg(el + s * HH + w * 4 + lane) + erv;
            aexp = __expf(leaky(e));
            zacc += aexp;
        }
        float alpha = __shfl_sync(0xffffffffu, aexp, hloc);
        float4 v = *(const float4*)(h + (size_t)s * DD + w * 128 + lane * 4);
        acc.x += alpha * v.x; acc.y += alpha * v.y;
        acc.z += alpha * v.z; acc.w += alpha * v.w;
    }
    float zinv = (lane < 4) ? (1.f / zacc) : 0.f;
    float zv = __shfl_sync(0xffffffffu, zinv, hloc);
    int c = w * 128 + lane * 4;
    const float4 bb = *(const float4*)(bias + c);
    float r0 = leaky(acc.x * zv + bb.x);
    float r1 = leaky(acc.y * zv + bb.y);
    float r2 = leaky(acc.z * zv + bb.z);
    float r3 = leaky(acc.w * zv + bb.w);
    if (outf) {
        *(float4*)(outf + (size_t)d * DD + c) = make_float4(r0, r1, r2, r3);
    } else {
        __half2 h0 = __floats2half2_rn(r0, r1);
        __half2 h1 = __floats2half2_rn(r2, r3);
        __half2 l0 = __floats2half2_rn(r0 - __half2float(h0.x), r1 - __half2float(h0.y));
        __half2 l1 = __floats2half2_rn(r2 - __half2float(h1.x), r3 - __half2float(h1.y));
        __half2* p = (__half2*)(outA + (size_t)d * KS + c);
        p[0] = h0; p[1] = h1;
        __half2* q = (__half2*)(outA + (size_t)d * KS + 256 + c);
        q[0] = l0; q[1] = l1;
    }
}

// ---------------- driver ----------------
extern "C" void kernel_launch(void* const* d_in, const int* in_sizes, int n_in,
                              void* d_out, int out_size) {
    const float* feats  = (const float*)d_in[0];
    const int*   src    = (const int*)d_in[1];
    const int*   dst    = (const int*)d_in[2];
    const float* proj_W = (const float*)d_in[3];
    const float* proj_b = (const float*)d_in[4];
    const float* Ws[2]  = { (const float*)d_in[5], (const float*)d_in[9] };
    const float* als[2] = { (const float*)d_in[6], (const float*)d_in[10] };
    const float* ars[2] = { (const float*)d_in[7], (const float*)d_in[11] };
    const float* bs[2]  = { (const float*)d_in[8], (const float*)d_in[12] };
    float* out = (float*)d_out;

    __half *Ab, *Bb;
    float *W01, *b01, *h, *el, *er;
    int *cnt, *bsum, *bpre, *off, *cur, *csr;
    cudaGetSymbolAddress((void**)&Ab, g_A);
    cudaGetSymbolAddress((void**)&Bb, g_B);
    cudaGetSymbolAddress((void**)&W01, g_W01);
    cudaGetSymbolAddress((void**)&b01, g_b01);
    cudaGetSymbolAddress((void**)&h, g_h);
    cudaGetSymbolAddress((void**)&el, g_el);
    cudaGetSymbolAddress((void**)&er, g_er);
    cudaGetSymbolAddress((void**)&cnt, g_cnt);
    cudaGetSymbolAddress((void**)&bsum, g_bsum);
    cudaGetSymbolAddress((void**)&bpre, g_bpre);
    cudaGetSymbolAddress((void**)&off, g_off);
    cudaGetSymbolAddress((void**)&cur, g_cur);
    cudaGetSymbolAddress((void**)&csr, g_csr);

    cudaFuncSetAttribute(gemm_fp16x2, cudaFuncAttributeMaxDynamicSharedMemorySize, 3 * STG);

    dim3 ggrid(DD / BN, NTILES);
    int gW = (DD * DD + 255) / 256;

    // 1: W01 = projW @ W1, b01 = proj_b @ W1 (fp32)
    wfuse<<<DD + 1, DD>>>(proj_W, Ws[0], proj_b, W01, b01);
    // 2-3: split inputs
    split_act<<<(NN * DD / 4 + 255) / 256, 256>>>(feats, Ab);
    split_w<<<gW, 256>>>(W01, Bb);
    // 4 (profiled): layer-0 h = feats @ W01 + b01, with el/er
    gemm_fp16x2<<<ggrid, 256, 3 * STG>>>(Ab, Bb, b01, h, als[0], ars[0], el, er);
    // 5-10: CSR build
    csr_init<<<(NN + 255) / 256, 256>>>(cnt);
    csr_hist<<<(EE + 255) / 256, 256>>>(dst, cnt);
    csr_scan1<<<NB, 256>>>(cnt, bsum);
    csr_scan2<<<1, 256>>>(bsum, bpre);
    csr_scan3<<<NB, 256>>>(cnt, bpre, off, cur);
    csr_scatter<<<(ET + 255) / 256, 256>>>(src, dst, cur, csr);
    // 11: layer-0 aggregation -> split A for layer 1
    agg_node<<<NN, 64>>>(off, csr, el, er, h, bs[0], nullptr, Ab);
    // 12-14: layer 1
    split_w<<<gW, 256>>>(Ws[1], Bb);
    gemm_fp16x2<<<ggrid, 256, 3 * STG>>>(Ab, Bb, nullptr, h, als[1], ars[1], el, er);
    agg_node<<<NN, 64>>>(off, csr, el, er, h, bs[1], out, nullptr);
}

// round 15
// speedup vs baseline: 1.0556x; 1.0556x over previous
#include <cuda_runtime.h>
#include <cuda_fp16.h>
#include <cstdint>

#define NN 50000
#define EE 500000
#define ET (EE + NN)
#define DD 256
#define HH 8
#define NEGS 0.2f

#define KS 512                  // A stored split-K: [0,256)=hi, [256,512)=lo (fp16)
#define KB 256                  // B stored single fp16
#define BM 128
#define BN 128
#define NCHUNK 8                // 2 passes x 4 chunks of K=64
#define NTILES ((NN + BM - 1) / BM)   // 391
#define MPAD (NTILES * BM)            // 50048
#define NB 196                  // scan blocks (ceil(NN/256))

// ---------------- scratch ----------------
__device__ __half g_A[(size_t)MPAD * KS];   // split activations
__device__ __half g_B[(size_t)DD * KB];     // fp16 weight, B^T layout [n][k]
__device__ float g_W01[DD * DD];            // fused projW@W1 (fp32)
__device__ float g_b01[DD];                 // proj_b@W1
__device__ float g_h[NN * DD];
__device__ float g_el[NN * HH];
__device__ float g_er[NN * HH];
__device__ int g_cnt[NN + 256];
__device__ int g_bsum[256];
__device__ int g_bpre[256];
__device__ int g_off[NN + 1];
__device__ int g_cur[NN];
__device__ int g_csr[ET];

__device__ __forceinline__ float leaky(float v) { return v > 0.f ? v : NEGS * v; }
__device__ __forceinline__ uint32_t smem_u32(const void* p) {
    return (uint32_t)__cvta_generic_to_shared(p);
}

// ---------------- fused weight: W01 = projW @ W1, b01 = proj_b @ W1 ----------------
__global__ void wfuse(const float* __restrict__ PW, const float* __restrict__ W1,
                      const float* __restrict__ pb, float* __restrict__ W01,
                      float* __restrict__ b01) {
    int m = blockIdx.x;          // 0..DD rows; block DD computes b01
    int n = threadIdx.x;
    if (m < DD) {
        float s = 0.f;
        #pragma unroll 4
        for (int j = 0; j < DD; j++)
            s += PW[m * DD + j] * W1[j * DD + n];
        W01[m * DD + n] = s;
    } else {
        float s = 0.f;
        #pragma unroll 4
        for (int j = 0; j < DD; j++)
            s += pb[j] * W1[j * DD + n];
        b01[n] = s;
    }
}

// ---------------- split kernels (fp32 -> fp16 hi/lo) ----------------
__global__ void split_act(const float* __restrict__ x, __half* __restrict__ A) {
    int i = blockIdx.x * blockDim.x + threadIdx.x;     // float4 idx
    if (i >= NN * DD / 4) return;
    int m = i >> 6, c = (i & 63) * 4;
    float4 v = ((const float4*)x)[i];
    __half2 h0 = __floats2half2_rn(v.x, v.y);
    __half2 h1 = __floats2half2_rn(v.z, v.w);
    __half2 l0 = __floats2half2_rn(v.x - __half2float(h0.x), v.y - __half2float(h0.y));
    __half2 l1 = __floats2half2_rn(v.z - __half2float(h1.x), v.w - __half2float(h1.y));
    __half2* p = (__half2*)(A + (size_t)m * KS + c);
    p[0] = h0; p[1] = h1;
    __half2* q = (__half2*)(A + (size_t)m * KS + 256 + c);
    q[0] = l0; q[1] = l1;
}
__global__ void split_w(const float* __restrict__ W, __half* __restrict__ Bm) {
    int i = blockIdx.x * blockDim.x + threadIdx.x;
    if (i >= DD * DD) return;
    int k = i >> 8, n = i & 255;           // W[k][n]
    Bm[(size_t)n * KB + k] = __float2half(W[i]);
}

// ---------------- CSR build ----------------
__global__ void csr_init(int* __restrict__ cnt) {
    int i = blockIdx.x * blockDim.x + threadIdx.x;
    if (i < NN) cnt[i] = 1;                 // self loop
}
__global__ void csr_hist(const int* __restrict__ dst, int* __restrict__ cnt) {
    int i = blockIdx.x * blockDim.x + threadIdx.x;
    if (i < EE) atomicAdd(&cnt[dst[i]], 1);
}
__global__ void csr_scan1(const int* __restrict__ cnt, int* __restrict__ bsum) {
    __shared__ int sd[256];
    int t = threadIdx.x, i = blockIdx.x * 256 + t;
    sd[t] = (i < NN) ? cnt[i] : 0;
    __syncthreads();
    for (int o = 128; o; o >>= 1) {
        if (t < o) sd[t] += sd[t + o];
        __syncthreads();
    }
    if (t == 0) bsum[blockIdx.x] = sd[0];
}
__global__ void csr_scan2(const int* __restrict__ bsum, int* __restrict__ bpre) {
    __shared__ int sd[256];
    int t = threadIdx.x;
    int v = (t < NB) ? bsum[t] : 0;
    sd[t] = v;
    __syncthreads();
    for (int o = 1; o < 256; o <<= 1) {
        int x = (t >= o) ? sd[t - o] : 0;
        __syncthreads();
        sd[t] += x;
        __syncthreads();
    }
    bpre[t] = sd[t] - v;                    // exclusive
}
__global__ void csr_scan3(const int* __restrict__ cnt, const int* __restrict__ bpre,
                          int* __restrict__ off, int* __restrict__ cur) {
    __shared__ int sd[256];
    int t = threadIdx.x, i = blockIdx.x * 256 + t;
    int v = (i < NN) ? cnt[i] : 0;
    sd[t] = v;
    __syncthreads();
    for (int o = 1; o < 256; o <<= 1) {
        int x = (t >= o) ? sd[t - o] : 0;
        __syncthreads();
        sd[t] += x;
        __syncthreads();
    }
    int ex = bpre[blockIdx.x] + sd[t] - v;
    if (i <= NN) {
        off[i] = ex;
        if (i < NN) cur[i] = ex;
    }
}
__global__ void csr_scatter(const int* __restrict__ src, const int* __restrict__ dst,
                            int* __restrict__ cur, int* __restrict__ csr) {
    int i = blockIdx.x * blockDim.x + threadIdx.x;
    if (i >= ET) return;
    int s = (i < EE) ? src[i] : (i - EE);
    int d = (i < EE) ? dst[i] : (i - EE);
    int pos = atomicAdd(&cur[d], 1);
    csr[pos] = s;
}

// ---------------- HMMA GEMM (BM=128, BN=128, 8 warps, 2-stage pipeline) ----------------
#define STG 32768

__device__ __forceinline__ void fill_stage(const __half* A, const __half* B,
                                           uint32_t aB, uint32_t bB,
                                           int m0, int n0, int c, int tid) {
    int kA = ((c >= 4) ? 256 : 0) + (c & 3) * 64;
    int kB = (c & 3) * 64;
    const char* Ag = (const char*)(A + (size_t)m0 * KS + kA);
    const char* Bg = (const char*)(B + (size_t)n0 * KB + kB);
    #pragma unroll
    for (int i = 0; i < 4; i++) {
        int u = tid + i * 256;
        int r = u >> 3, s = u & 7;
        uint32_t off = (uint32_t)r * 128 + (uint32_t)((s ^ (r & 7)) << 4);
        unsigned long long sa = __cvta_generic_to_global(Ag + (size_t)r * 1024 + s * 16);
        unsigned long long sbg = __cvta_generic_to_global(Bg + (size_t)r * 512 + s * 16);
        asm volatile("cp.async.cg.shared.global [%0], [%1], 16;" :: "r"(aB + off), "l"(sa));
        asm volatile("cp.async.cg.shared.global [%0], [%1], 16;" :: "r"(bB + off), "l"(sbg));
    }
}

__device__ __forceinline__ void mma16816(float* d, const uint32_t* a, const uint32_t* b) {
    asm volatile("mma.sync.aligned.m16n8k16.row.col.f32.f16.f16.f32 "
                 "{%0,%1,%2,%3}, {%4,%5,%6,%7}, {%8,%9}, {%0,%1,%2,%3};"
                 : "+f"(d[0]), "+f"(d[1]), "+f"(d[2]), "+f"(d[3])
                 : "r"(a[0]), "r"(a[1]), "r"(a[2]), "r"(a[3]), "r"(b[0]), "r"(b[1]));
}

__global__ void __launch_bounds__(256, 2)
gemm_fp16x2(const __half* __restrict__ A, const __half* __restrict__ B,
            const float* __restrict__ bias, float* __restrict__ outf,
            const float* __restrict__ al, const float* __restrict__ ar,
            float* __restrict__ el, float* __restrict__ er) {
    extern __shared__ char smem[];
    uint32_t sb = smem_u32(smem);
    int tid = threadIdx.x, wid = tid >> 5, lane = tid & 31;
    int m0 = blockIdx.y * BM, n0 = blockIdx.x * BN;
    int warp_m = (wid & 3) * 32, warp_n = (wid >> 2) * 64;

    float acc[2][8][4];
    #pragma unroll
    for (int mt = 0; mt < 2; mt++)
        #pragma unroll
        for (int nt = 0; nt < 8; nt++)
            #pragma unroll
            for (int q = 0; q < 4; q++) acc[mt][nt][q] = 0.f;

    fill_stage(A, B, sb, sb + 16384, m0, n0, 0, tid);
    asm volatile("cp.async.commit_group;" ::: "memory");

    for (int c = 0; c < NCHUNK; c++) {
        if (c + 1 < NCHUNK) {
            uint32_t st = ((c + 1) & 1) * STG;
            fill_stage(A, B, sb + st, sb + st + 16384, m0, n0, c + 1, tid);
            asm volatile("cp.async.commit_group;" ::: "memory");
            asm volatile("cp.async.wait_group 1;" ::: "memory");
        } else {
            asm volatile("cp.async.wait_group 0;" ::: "memory");
        }
        __syncthreads();
        uint32_t as = sb + (c & 1) * STG;
        uint32_t bs = as + 16384;
        #pragma unroll
        for (int kk = 0; kk < 4; kk++) {
            uint32_t a[2][4], b[8][2];
            {
                int rr = lane & 15, half = lane >> 4;
                int s = kk * 2 + half;
                #pragma unroll
                for (int mt = 0; mt < 2; mt++) {
                    int row = warp_m + mt * 16 + rr;
                    uint32_t ad = as + (uint32_t)row * 128 + (uint32_t)((s ^ (row & 7)) << 4);
                    asm volatile("ldmatrix.sync.aligned.m8n8.x4.shared.b16 {%0,%1,%2,%3}, [%4];"
                                 : "=r"(a[mt][0]), "=r"(a[mt][1]), "=r"(a[mt][2]), "=r"(a[mt][3])
                                 : "r"(ad));
                }
            }
            {
                int half = (lane >> 3) & 1;
                int s = kk * 2 + half;
                int nro = ((lane >> 4) << 3) + (lane & 7);
                #pragma unroll
                for (int j = 0; j < 4; j++) {
                    int row = warp_n + j * 16 + nro;
                    uint32_t bd = bs + (uint32_t)row * 128 + (uint32_t)((s ^ (row & 7)) << 4);
                    asm volatile("ldmatrix.sync.aligned.m8n8.x4.shared.b16 {%0,%1,%2,%3}, [%4];"
                                 : "=r"(b[2*j][0]), "=r"(b[2*j][1]), "=r"(b[2*j+1][0]), "=r"(b[2*j+1][1])
                                 : "r"(bd));
                }
            }
            #pragma unroll
            for (int mt = 0; mt < 2; mt++)
                #pragma unroll
                for (int nt = 0; nt < 8; nt++)
                    mma16816(acc[mt][nt], a[mt], b[nt]);
        }
        __syncthreads();
    }

    // ---------------- epilogue ----------------
    int rin = lane >> 2, colq = (lane & 3) * 2;
    if (bias) {
        #pragma unroll
        for (int nt = 0; nt < 8; nt++) {
            int cb = n0 + warp_n + nt * 8 + colq;
            float b0 = __ldg(bias + cb), b1 = __ldg(bias + cb + 1);
            #pragma unroll
            for (int mt = 0; mt < 2; mt++) {
                acc[mt][nt][0] += b0; acc[mt][nt][1] += b1;
                acc[mt][nt][2] += b0; acc[mt][nt][3] += b1;
            }
        }
    }
    #pragma unroll
    for (int mt = 0; mt < 2; mt++) {
        int r0 = m0 + warp_m + mt * 16 + rin;
        #pragma unroll
        for (int nt = 0; nt < 8; nt++) {
            int cb = n0 + warp_n + nt * 8 + colq;
            if (r0 < NN)
                *(float2*)(outf + (size_t)r0 * DD + cb) =
                    make_float2(acc[mt][nt][0], acc[mt][nt][1]);
            if (r0 + 8 < NN)
                *(float2*)(outf + (size_t)(r0 + 8) * DD + cb) =
                    make_float2(acc[mt][nt][2], acc[mt][nt][3]);
        }
        #pragma unroll
        for (int hh2 = 0; hh2 < 2; hh2++) {
            int ghead = (n0 + warp_n + hh2 * 32) >> 5;
            float sl0 = 0.f, sr0 = 0.f, sl1 = 0.f, sr1 = 0.f;
            #pragma unroll
            for (int t = 0; t < 4; t++) {
                int nt = hh2 * 4 + t;
                int cg = n0 + warp_n + nt * 8 + colq;
                float w0 = __ldg(al + cg), w1 = __ldg(al + cg + 1);
                float u0 = __ldg(ar + cg), u1 = __ldg(ar + cg + 1);
                sl0 += acc[mt][nt][0] * w0 + acc[mt][nt][1] * w1;
                sr0 += acc[mt][nt][0] * u0 + acc[mt][nt][1] * u1;
                sl1 += acc[mt][nt][2] * w0 + acc[mt][nt][3] * w1;
                sr1 += acc[mt][nt][2] * u0 + acc[mt][nt][3] * u1;
            }
            #pragma unroll
            for (int o = 1; o < 4; o <<= 1) {
                sl0 += __shfl_xor_sync(0xffffffffu, sl0, o);
                sr0 += __shfl_xor_sync(0xffffffffu, sr0, o);
                sl1 += __shfl_xor_sync(0xffffffffu, sl1, o);
                sr1 += __shfl_xor_sync(0xffffffffu, sr1, o);
            }
            if (colq == 0) {
                if (r0 < NN) { el[r0 * HH + ghead] = sl0; er[r0 * HH + ghead] = sr0; }
                if (r0 + 8 < NN) { el[(r0 + 8) * HH + ghead] = sl1; er[(r0 + 8) * HH + ghead] = sr1; }
            }
        }
    }
}

// ---------------- CSR aggregation: block per dst node, 64 threads ----------------
__global__ void __launch_bounds__(64)
agg_node(const int* __restrict__ off, const int* __restrict__ csr,
         const float* __restrict__ el, const float* __restrict__ er,
         const float* __restrict__ h, const float* __restrict__ bias,
         float* __restrict__ outf, __half* __restrict__ outA) {
    int d = blockIdx.x;
    int tid = threadIdx.x, w = tid >> 5, lane = tid & 31;
    int beg = __ldg(off + d), end = __ldg(off + d + 1);
    int hloc = lane >> 3;
    float erv = (lane < 4) ? __ldg(er + d * HH + w * 4 + lane) : 0.f;
    float4 acc = make_float4(0.f, 0.f, 0.f, 0.f);
    float zacc = 0.f;
    for (int j = beg; j < end; j++) {
        int s = __ldg(csr + j);
        float aexp = 0.f;
        if (lane < 4) {
            float e = __ldg(el + s * HH + w * 4 + lane) + erv;
            aexp = __expf(leaky(e));
            zacc += aexp;
        }
        float alpha = __shfl_sync(0xffffffffu, aexp, hloc);
        float4 v = *(const float4*)(h + (size_t)s * DD + w * 128 + lane * 4);
        acc.x += alpha * v.x; acc.y += alpha * v.y;
        acc.z += alpha * v.z; acc.w += alpha * v.w;
    }
    float zinv = (lane < 4) ? (1.f / zacc) : 0.f;
    float zv = __shfl_sync(0xffffffffu, zinv, hloc);
    int c = w * 128 + lane * 4;
    const float4 bb = *(const float4*)(bias + c);
    float r0 = leaky(acc.x * zv + bb.x);
    float r1 = leaky(acc.y * zv + bb.y);
    float r2 = leaky(acc.z * zv + bb.z);
    float r3 = leaky(acc.w * zv + bb.w);
    if (outf) {
        *(float4*)(outf + (size_t)d * DD + c) = make_float4(r0, r1, r2, r3);
    } else {
        __half2 h0 = __floats2half2_rn(r0, r1);
        __half2 h1 = __floats2half2_rn(r2, r3);
        __half2 l0 = __floats2half2_rn(r0 - __half2float(h0.x), r1 - __half2float(h0.y));
        __half2 l1 = __floats2half2_rn(r2 - __half2float(h1.x), r3 - __half2float(h1.y));
        __half2* p = (__half2*)(outA + (size_t)d * KS + c);
        p[0] = h0; p[1] = h1;
        __half2* q = (__half2*)(outA + (size_t)d * KS + 256 + c);
        q[0] = l0; q[1] = l1;
    }
}

// ---------------- driver ----------------
extern "C" void kernel_launch(void* const* d_in, const int* in_sizes, int n_in,
                              void* d_out, int out_size) {
    const float* feats  = (const float*)d_in[0];
    const int*   src    = (const int*)d_in[1];
    const int*   dst    = (const int*)d_in[2];
    const float* proj_W = (const float*)d_in[3];
    const float* proj_b = (const float*)d_in[4];
    const float* Ws[2]  = { (const float*)d_in[5], (const float*)d_in[9] };
    const float* als[2] = { (const float*)d_in[6], (const float*)d_in[10] };
    const float* ars[2] = { (const float*)d_in[7], (const float*)d_in[11] };
    const float* bs[2]  = { (const float*)d_in[8], (const float*)d_in[12] };
    float* out = (float*)d_out;

    __half *Ab, *Bb;
    float *W01, *b01, *h, *el, *er;
    int *cnt, *bsum, *bpre, *off, *cur, *csr;
    cudaGetSymbolAddress((void**)&Ab, g_A);
    cudaGetSymbolAddress((void**)&Bb, g_B);
    cudaGetSymbolAddress((void**)&W01, g_W01);
    cudaGetSymbolAddress((void**)&b01, g_b01);
    cudaGetSymbolAddress((void**)&h, g_h);
    cudaGetSymbolAddress((void**)&el, g_el);
    cudaGetSymbolAddress((void**)&er, g_er);
    cudaGetSymbolAddress((void**)&cnt, g_cnt);
    cudaGetSymbolAddress((void**)&bsum, g_bsum);
    cudaGetSymbolAddress((void**)&bpre, g_bpre);
    cudaGetSymbolAddress((void**)&off, g_off);
    cudaGetSymbolAddress((void**)&cur, g_cur);
    cudaGetSymbolAddress((void**)&csr, g_csr);

    static cudaStream_t s2 = nullptr;
    static cudaEvent_t evFork = nullptr, evCsr = nullptr;
    if (!s2) {
        cudaStreamCreateWithFlags(&s2, cudaStreamNonBlocking);
        cudaEventCreateWithFlags(&evFork, cudaEventDisableTiming);
        cudaEventCreateWithFlags(&evCsr, cudaEventDisableTiming);
        cudaFuncSetAttribute(gemm_fp16x2, cudaFuncAttributeMaxDynamicSharedMemorySize, 2 * STG);
    }

    dim3 ggrid(DD / BN, NTILES);
    int gW = (DD * DD + 255) / 256;

    // fork: CSR chain on side stream (independent of GEMM path)
    cudaEventRecord(evFork, 0);
    cudaStreamWaitEvent(s2, evFork, 0);
    csr_init<<<(NN + 255) / 256, 256, 0, s2>>>(cnt);
    csr_hist<<<(EE + 255) / 256, 256, 0, s2>>>(dst, cnt);
    csr_scan1<<<NB, 256, 0, s2>>>(cnt, bsum);
    csr_scan2<<<1, 256, 0, s2>>>(bsum, bpre);
    csr_scan3<<<NB, 256, 0, s2>>>(cnt, bpre, off, cur);
    csr_scatter<<<(ET + 255) / 256, 256, 0, s2>>>(src, dst, cur, csr);
    cudaEventRecord(evCsr, s2);

    // main stream: weight fuse + splits + layer-0 GEMM
    wfuse<<<DD + 1, DD>>>(proj_W, Ws[0], proj_b, W01, b01);
    split_act<<<(NN * DD / 4 + 255) / 256, 256>>>(feats, Ab);
    split_w<<<gW, 256>>>(W01, Bb);
    gemm_fp16x2<<<ggrid, 256, 2 * STG>>>(Ab, Bb, b01, h, als[0], ars[0], el, er);

    // join: aggregation needs the CSR
    cudaStreamWaitEvent(0, evCsr, 0);
    agg_node<<<NN, 64>>>(off, csr, el, er, h, bs[0], nullptr, Ab);
    // layer 1
    split_w<<<gW, 256>>>(Ws[1], Bb);
    gemm_fp16x2<<<ggrid, 256, 2 * STG>>>(Ab, Bb, nullptr, h, als[1], ars[1], el, er);
    agg_node<<<NN, 64>>>(off, csr, el, er, h, bs[1], out, nullptr);
}

// round 17
// speedup vs baseline: 1.2184x; 1.1541x over previous
#include <cuda_runtime.h>
#include <cuda_fp16.h>
#include <cstdint>

#define NN 50000
#define EE 500000
#define ET (EE + NN)
#define DD 256
#define HH 8
#define NEGS 0.2f

#define KS 256                  // A stored plain fp16, K=256
#define KB 256                  // B stored single fp16
#define BM 128
#define BN 128
#define NCHUNK 4                // 4 chunks of K=64
#define NTILES ((NN + BM - 1) / BM)   // 391
#define MPAD (NTILES * BM)            // 50048
#define NB 196                  // scan blocks (ceil(NN/256))

// ---------------- scratch ----------------
__device__ __half g_A[(size_t)MPAD * KS];   // fp16 activations
__device__ __half g_B[(size_t)DD * KB];     // fp16 weight, B^T layout [n][k]
__device__ float g_W01[DD * DD];            // fused projW@W1 (fp32)
__device__ float g_b01[DD];                 // proj_b@W1
__device__ float g_h[NN * DD];
__device__ float g_el[NN * HH];
__device__ float g_er[NN * HH];
__device__ int g_cnt[NN + 256];
__device__ int g_bsum[256];
__device__ int g_bpre[256];
__device__ int g_off[NN + 1];
__device__ int g_cur[NN];
__device__ int g_csr[ET];

__device__ __forceinline__ float leaky(float v) { return v > 0.f ? v : NEGS * v; }
__device__ __forceinline__ uint32_t smem_u32(const void* p) {
    return (uint32_t)__cvta_generic_to_shared(p);
}

// ---------------- fused weight: W01 = projW @ W1, b01 = proj_b @ W1 ----------------
__global__ void wfuse(const float* __restrict__ PW, const float* __restrict__ W1,
                      const float* __restrict__ pb, float* __restrict__ W01,
                      float* __restrict__ b01) {
    int m = blockIdx.x;          // 0..DD rows; block DD computes b01
    int n = threadIdx.x;
    if (m < DD) {
        float s = 0.f;
        #pragma unroll 4
        for (int j = 0; j < DD; j++)
            s += PW[m * DD + j] * W1[j * DD + n];
        W01[m * DD + n] = s;
    } else {
        float s = 0.f;
        #pragma unroll 4
        for (int j = 0; j < DD; j++)
            s += pb[j] * W1[j * DD + n];
        b01[n] = s;
    }
}

// ---------------- convert kernels (fp32 -> fp16) ----------------
__global__ void split_act(const float* __restrict__ x, __half* __restrict__ A) {
    int i = blockIdx.x * blockDim.x + threadIdx.x;     // float4 idx
    if (i >= NN * DD / 4) return;
    float4 v = ((const float4*)x)[i];
    __half2 h0 = __floats2half2_rn(v.x, v.y);
    __half2 h1 = __floats2half2_rn(v.z, v.w);
    __half2* p = (__half2*)(A + (size_t)i * 4);
    p[0] = h0; p[1] = h1;
}
__global__ void split_w(const float* __restrict__ W, __half* __restrict__ Bm) {
    int i = blockIdx.x * blockDim.x + threadIdx.x;
    if (i >= DD * DD) return;
    int k = i >> 8, n = i & 255;           // W[k][n]
    Bm[(size_t)n * KB + k] = __float2half(W[i]);
}

// ---------------- CSR build ----------------
__global__ void csr_init(int* __restrict__ cnt) {
    int i = blockIdx.x * blockDim.x + threadIdx.x;
    if (i < NN) cnt[i] = 1;                 // self loop
}
__global__ void csr_hist(const int* __restrict__ dst, int* __restrict__ cnt) {
    int i = blockIdx.x * blockDim.x + threadIdx.x;
    if (i < EE) atomicAdd(&cnt[dst[i]], 1);
}
__global__ void csr_scan1(const int* __restrict__ cnt, int* __restrict__ bsum) {
    __shared__ int sd[256];
    int t = threadIdx.x, i = blockIdx.x * 256 + t;
    sd[t] = (i < NN) ? cnt[i] : 0;
    __syncthreads();
    for (int o = 128; o; o >>= 1) {
        if (t < o) sd[t] += sd[t + o];
        __syncthreads();
    }
    if (t == 0) bsum[blockIdx.x] = sd[0];
}
__global__ void csr_scan2(const int* __restrict__ bsum, int* __restrict__ bpre) {
    __shared__ int sd[256];
    int t = threadIdx.x;
    int v = (t < NB) ? bsum[t] : 0;
    sd[t] = v;
    __syncthreads();
    for (int o = 1; o < 256; o <<= 1) {
        int x = (t >= o) ? sd[t - o] : 0;
        __syncthreads();
        sd[t] += x;
        __syncthreads();
    }
    bpre[t] = sd[t] - v;                    // exclusive
}
__global__ void csr_scan3(const int* __restrict__ cnt, const int* __restrict__ bpre,
                          int* __restrict__ off, int* __restrict__ cur) {
    __shared__ int sd[256];
    int t = threadIdx.x, i = blockIdx.x * 256 + t;
    int v = (i < NN) ? cnt[i] : 0;
    sd[t] = v;
    __syncthreads();
    for (int o = 1; o < 256; o <<= 1) {
        int x = (t >= o) ? sd[t - o] : 0;
        __syncthreads();
        sd[t] += x;
        __syncthreads();
    }
    int ex = bpre[blockIdx.x] + sd[t] - v;
    if (i <= NN) {
        off[i] = ex;
        if (i < NN) cur[i] = ex;
    }
}
__global__ void csr_scatter(const int* __restrict__ src, const int* __restrict__ dst,
                            int* __restrict__ cur, int* __restrict__ csr) {
    int i = blockIdx.x * blockDim.x + threadIdx.x;
    if (i >= ET) return;
    int s = (i < EE) ? src[i] : (i - EE);
    int d = (i < EE) ? dst[i] : (i - EE);
    int pos = atomicAdd(&cur[d], 1);
    csr[pos] = s;
}

// ---------------- HMMA GEMM (BM=128, BN=128, 8 warps, 2-stage pipeline, K=256) ----------------
#define STG 32768

__device__ __forceinline__ void fill_stage(const __half* A, const __half* B,
                                           uint32_t aB, uint32_t bB,
                                           int m0, int n0, int c, int tid) {
    int k0 = c * 64;
    const char* Ag = (const char*)(A + (size_t)m0 * KS + k0);
    const char* Bg = (const char*)(B + (size_t)n0 * KB + k0);
    #pragma unroll
    for (int i = 0; i < 4; i++) {
        int u = tid + i * 256;
        int r = u >> 3, s = u & 7;
        uint32_t off = (uint32_t)r * 128 + (uint32_t)((s ^ (r & 7)) << 4);
        unsigned long long sa = __cvta_generic_to_global(Ag + (size_t)r * 512 + s * 16);
        unsigned long long sbg = __cvta_generic_to_global(Bg + (size_t)r * 512 + s * 16);
        asm volatile("cp.async.cg.shared.global [%0], [%1], 16;" :: "r"(aB + off), "l"(sa));
        asm volatile("cp.async.cg.shared.global [%0], [%1], 16;" :: "r"(bB + off), "l"(sbg));
    }
}

__device__ __forceinline__ void mma16816(float* d, const uint32_t* a, const uint32_t* b) {
    asm volatile("mma.sync.aligned.m16n8k16.row.col.f32.f16.f16.f32 "
                 "{%0,%1,%2,%3}, {%4,%5,%6,%7}, {%8,%9}, {%0,%1,%2,%3};"
                 : "+f"(d[0]), "+f"(d[1]), "+f"(d[2]), "+f"(d[3])
                 : "r"(a[0]), "r"(a[1]), "r"(a[2]), "r"(a[3]), "r"(b[0]), "r"(b[1]));
}

__global__ void __launch_bounds__(256, 2)
gemm_fp16(const __half* __restrict__ A, const __half* __restrict__ B,
          const float* __restrict__ bias, float* __restrict__ outf,
          const float* __restrict__ al, const float* __restrict__ ar,
          float* __restrict__ el, float* __restrict__ er) {
    extern __shared__ char smem[];
    uint32_t sb = smem_u32(smem);
    int tid = threadIdx.x, wid = tid >> 5, lane = tid & 31;
    int m0 = blockIdx.y * BM, n0 = blockIdx.x * BN;
    int warp_m = (wid & 3) * 32, warp_n = (wid >> 2) * 64;

    float acc[2][8][4];
    #pragma unroll
    for (int mt = 0; mt < 2; mt++)
        #pragma unroll
        for (int nt = 0; nt < 8; nt++)
            #pragma unroll
            for (int q = 0; q < 4; q++) acc[mt][nt][q] = 0.f;

    fill_stage(A, B, sb, sb + 16384, m0, n0, 0, tid);
    asm volatile("cp.async.commit_group;" ::: "memory");

    for (int c = 0; c < NCHUNK; c++) {
        if (c + 1 < NCHUNK) {
            uint32_t st = ((c + 1) & 1) * STG;
            fill_stage(A, B, sb + st, sb + st + 16384, m0, n0, c + 1, tid);
            asm volatile("cp.async.commit_group;" ::: "memory");
            asm volatile("cp.async.wait_group 1;" ::: "memory");
        } else {
            asm volatile("cp.async.wait_group 0;" ::: "memory");
        }
        __syncthreads();
        uint32_t as = sb + (c & 1) * STG;
        uint32_t bs = as + 16384;
        #pragma unroll
        for (int kk = 0; kk < 4; kk++) {
            uint32_t a[2][4], b[8][2];
            {
                int rr = lane & 15, half = lane >> 4;
                int s = kk * 2 + half;
                #pragma unroll
                for (int mt = 0; mt < 2; mt++) {
                    int row = warp_m + mt * 16 + rr;
                    uint32_t ad = as + (uint32_t)row * 128 + (uint32_t)((s ^ (row & 7)) << 4);
                    asm volatile("ldmatrix.sync.aligned.m8n8.x4.shared.b16 {%0,%1,%2,%3}, [%4];"
                                 : "=r"(a[mt][0]), "=r"(a[mt][1]), "=r"(a[mt][2]), "=r"(a[mt][3])
                                 : "r"(ad));
                }
            }
            {
                int half = (lane >> 3) & 1;
                int s = kk * 2 + half;
                int nro = ((lane >> 4) << 3) + (lane & 7);
                #pragma unroll
                for (int j = 0; j < 4; j++) {
                    int row = warp_n + j * 16 + nro;
                    uint32_t bd = bs + (uint32_t)row * 128 + (uint32_t)((s ^ (row & 7)) << 4);
                    asm volatile("ldmatrix.sync.aligned.m8n8.x4.shared.b16 {%0,%1,%2,%3}, [%4];"
                                 : "=r"(b[2*j][0]), "=r"(b[2*j][1]), "=r"(b[2*j+1][0]), "=r"(b[2*j+1][1])
                                 : "r"(bd));
                }
            }
            #pragma unroll
            for (int mt = 0; mt < 2; mt++)
                #pragma unroll
                for (int nt = 0; nt < 8; nt++)
                    mma16816(acc[mt][nt], a[mt], b[nt]);
        }
        __syncthreads();
    }

    // ---------------- epilogue ----------------
    int rin = lane >> 2, colq = (lane & 3) * 2;
    if (bias) {
        #pragma unroll
        for (int nt = 0; nt < 8; nt++) {
            int cb = n0 + warp_n + nt * 8 + colq;
            float b0 = __ldg(bias + cb), b1 = __ldg(bias + cb + 1);
            #pragma unroll
            for (int mt = 0; mt < 2; mt++) {
                acc[mt][nt][0] += b0; acc[mt][nt][1] += b1;
                acc[mt][nt][2] += b0; acc[mt][nt][3] += b1;
            }
        }
    }
    #pragma unroll
    for (int mt = 0; mt < 2; mt++) {
        int r0 = m0 + warp_m + mt * 16 + rin;
        #pragma unroll
        for (int nt = 0; nt < 8; nt++) {
            int cb = n0 + warp_n + nt * 8 + colq;
            if (r0 < NN)
                *(float2*)(outf + (size_t)r0 * DD + cb) =
                    make_float2(acc[mt][nt][0], acc[mt][nt][1]);
            if (r0 + 8 < NN)
                *(float2*)(outf + (size_t)(r0 + 8) * DD + cb) =
                    make_float2(acc[mt][nt][2], acc[mt][nt][3]);
        }
        #pragma unroll
        for (int hh2 = 0; hh2 < 2; hh2++) {
            int ghead = (n0 + warp_n + hh2 * 32) >> 5;
            float sl0 = 0.f, sr0 = 0.f, sl1 = 0.f, sr1 = 0.f;
            #pragma unroll
            for (int t = 0; t < 4; t++) {
                int nt = hh2 * 4 + t;
                int cg = n0 + warp_n + nt * 8 + colq;
                float w0 = __ldg(al + cg), w1 = __ldg(al + cg + 1);
                float u0 = __ldg(ar + cg), u1 = __ldg(ar + cg + 1);
                sl0 += acc[mt][nt][0] * w0 + acc[mt][nt][1] * w1;
                sr0 += acc[mt][nt][0] * u0 + acc[mt][nt][1] * u1;
                sl1 += acc[mt][nt][2] * w0 + acc[mt][nt][3] * w1;
                sr1 += acc[mt][nt][2] * u0 + acc[mt][nt][3] * u1;
            }
            #pragma unroll
            for (int o = 1; o < 4; o <<= 1) {
                sl0 += __shfl_xor_sync(0xffffffffu, sl0, o);
                sr0 += __shfl_xor_sync(0xffffffffu, sr0, o);
                sl1 += __shfl_xor_sync(0xffffffffu, sl1, o);
                sr1 += __shfl_xor_sync(0xffffffffu, sr1, o);
            }
            if (colq == 0) {
                if (r0 < NN) { el[r0 * HH + ghead] = sl0; er[r0 * HH + ghead] = sr0; }
                if (r0 + 8 < NN) { el[(r0 + 8) * HH + ghead] = sl1; er[(r0 + 8) * HH + ghead] = sr1; }
            }
        }
    }
}

// ---------------- CSR aggregation: block per dst node, 64 threads ----------------
__global__ void __launch_bounds__(64)
agg_node(const int* __restrict__ off, const int* __restrict__ csr,
         const float* __restrict__ el, const float* __restrict__ er,
         const float* __restrict__ h, const float* __restrict__ bias,
         float* __restrict__ outf, __half* __restrict__ outA) {
    int d = blockIdx.x;
    int tid = threadIdx.x, w = tid >> 5, lane = tid & 31;
    int beg = __ldg(off + d), end = __ldg(off + d + 1);
    int hloc = lane >> 3;
    float erv = (lane < 4) ? __ldg(er + d * HH + w * 4 + lane) : 0.f;
    float4 acc = make_float4(0.f, 0.f, 0.f, 0.f);
    float zacc = 0.f;
    for (int j = beg; j < end; j++) {
        int s = __ldg(csr + j);
        float aexp = 0.f;
        if (lane < 4) {
            float e = __ldg(el + s * HH + w * 4 + lane) + erv;
            aexp = __expf(leaky(e));
            zacc += aexp;
        }
        float alpha = __shfl_sync(0xffffffffu, aexp, hloc);
        float4 v = *(const float4*)(h + (size_t)s * DD + w * 128 + lane * 4);
        acc.x += alpha * v.x; acc.y += alpha * v.y;
        acc.z += alpha * v.z; acc.w += alpha * v.w;
    }
    float zinv = (lane < 4) ? (1.f / zacc) : 0.f;
    float zv = __shfl_sync(0xffffffffu, zinv, hloc);
    int c = w * 128 + lane * 4;
    const float4 bb = *(const float4*)(bias + c);
    float r0 = leaky(acc.x * zv + bb.x);
    float r1 = leaky(acc.y * zv + bb.y);
    float r2 = leaky(acc.z * zv + bb.z);
    float r3 = leaky(acc.w * zv + bb.w);
    if (outf) {
        *(float4*)(outf + (size_t)d * DD + c) = make_float4(r0, r1, r2, r3);
    } else {
        __half2 h0 = __floats2half2_rn(r0, r1);
        __half2 h1 = __floats2half2_rn(r2, r3);
        __half2* p = (__half2*)(outA + (size_t)d * KS + c);
        p[0] = h0; p[1] = h1;
    }
}

// ---------------- driver ----------------
extern "C" void kernel_launch(void* const* d_in, const int* in_sizes, int n_in,
                              void* d_out, int out_size) {
    const float* feats  = (const float*)d_in[0];
    const int*   src    = (const int*)d_in[1];
    const int*   dst    = (const int*)d_in[2];
    const float* proj_W = (const float*)d_in[3];
    const float* proj_b = (const float*)d_in[4];
    const float* Ws[2]  = { (const float*)d_in[5], (const float*)d_in[9] };
    const float* als[2] = { (const float*)d_in[6], (const float*)d_in[10] };
    const float* ars[2] = { (const float*)d_in[7], (const float*)d_in[11] };
    const float* bs[2]  = { (const float*)d_in[8], (const float*)d_in[12] };
    float* out = (float*)d_out;

    __half *Ab, *Bb;
    float *W01, *b01, *h, *el, *er;
    int *cnt, *bsum, *bpre, *off, *cur, *csr;
    cudaGetSymbolAddress((void**)&Ab, g_A);
    cudaGetSymbolAddress((void**)&Bb, g_B);
    cudaGetSymbolAddress((void**)&W01, g_W01);
    cudaGetSymbolAddress((void**)&b01, g_b01);
    cudaGetSymbolAddress((void**)&h, g_h);
    cudaGetSymbolAddress((void**)&el, g_el);
    cudaGetSymbolAddress((void**)&er, g_er);
    cudaGetSymbolAddress((void**)&cnt, g_cnt);
    cudaGetSymbolAddress((void**)&bsum, g_bsum);
    cudaGetSymbolAddress((void**)&bpre, g_bpre);
    cudaGetSymbolAddress((void**)&off, g_off);
    cudaGetSymbolAddress((void**)&cur, g_cur);
    cudaGetSymbolAddress((void**)&csr, g_csr);

    static cudaStream_t s2 = nullptr;
    static cudaEvent_t evFork = nullptr, evCsr = nullptr;
    if (!s2) {
        cudaStreamCreateWithFlags(&s2, cudaStreamNonBlocking);
        cudaEventCreateWithFlags(&evFork, cudaEventDisableTiming);
        cudaEventCreateWithFlags(&evCsr, cudaEventDisableTiming);
        cudaFuncSetAttribute(gemm_fp16, cudaFuncAttributeMaxDynamicSharedMemorySize, 2 * STG);
    }

    dim3 ggrid(DD / BN, NTILES);
    int gW = (DD * DD + 255) / 256;

    // fork: CSR chain on side stream (independent of GEMM path)
    cudaEventRecord(evFork, 0);
    cudaStreamWaitEvent(s2, evFork, 0);
    csr_init<<<(NN + 255) / 256, 256, 0, s2>>>(cnt);
    csr_hist<<<(EE + 255) / 256, 256, 0, s2>>>(dst, cnt);
    csr_scan1<<<NB, 256, 0, s2>>>(cnt, bsum);
    csr_scan2<<<1, 256, 0, s2>>>(bsum, bpre);
    csr_scan3<<<NB, 256, 0, s2>>>(cnt, bpre, off, cur);
    csr_scatter<<<(ET + 255) / 256, 256, 0, s2>>>(src, dst, cur, csr);
    cudaEventRecord(evCsr, s2);

    // main stream: weight fuse + converts + layer-0 GEMM
    wfuse<<<DD + 1, DD>>>(proj_W, Ws[0], proj_b, W01, b01);
    split_act<<<(NN * DD / 4 + 255) / 256, 256>>>(feats, Ab);
    split_w<<<gW, 256>>>(W01, Bb);
    gemm_fp16<<<ggrid, 256, 2 * STG>>>(Ab, Bb, b01, h, als[0], ars[0], el, er);

    // join: aggregation needs the CSR
    cudaStreamWaitEvent(0, evCsr, 0);
    agg_node<<<NN, 64>>>(off, csr, el, er, h, bs[0], nullptr, Ab);
    // layer 1
    split_w<<<gW, 256>>>(Ws[1], Bb);
    gemm_fp16<<<ggrid, 256, 2 * STG>>>(Ab, Bb, nullptr, h, als[1], ars[1], el, er);
    agg_node<<<NN, 64>>>(off, csr, el, er, h, bs[1], out, nullptr);
}